// round 16
// baseline (speedup 1.0000x reference)
#include <cuda_runtime.h>
#include <math.h>

// Problem constants
#define BB 2
#define SS 2048
#define EE 1024
#define HH 16
#define HD 64
#define SCALE 0.125f   // 1/sqrt(64)

typedef unsigned long long ull;
typedef unsigned int uint;

#define CVT_TF32(u, f) asm("cvt.rna.tf32.f32 %0, %1;" : "=r"(u) : "f"(f))

// cp.async helpers (sm_80+; .cg = L1-bypass 16B)
__device__ __forceinline__ uint sm_u32(const void* p) { return (uint)__cvta_generic_to_shared(p); }
#define CPA16(d, s)   asm volatile("cp.async.cg.shared.global [%0], [%1], 16;" :: "r"(d), "l"(s))
#define CPA_COMMIT()  asm volatile("cp.async.commit_group;" ::: "memory")
#define CPA_WAIT0()   asm volatile("cp.async.wait_group 0;" ::: "memory")

// mma.sync m16n8k8 tf32: C(16x8,f32) += A(16x8,tf32) * B(8x8,tf32)
// A row-major frag: a0=(g,q) a1=(g+8,q) a2=(g,q+4) a3=(g+8,q+4); g=lane>>2, q=lane&3
// B col-major frag: b0=(k=q, n=g) b1=(k=q+4, n=g)
// C frag: c0=(g,2q) c1=(g,2q+1) c2=(g+8,2q) c3=(g+8,2q+1)
__device__ __forceinline__ void mma_tf32(float* c, const uint* a, uint b0, uint b1) {
    asm volatile("mma.sync.aligned.m16n8k8.row.col.f32.tf32.tf32.f32 "
        "{%0,%1,%2,%3}, {%4,%5,%6,%7}, {%8,%9}, {%0,%1,%2,%3};"
        : "+f"(c[0]), "+f"(c[1]), "+f"(c[2]), "+f"(c[3])
        : "r"(a[0]), "r"(a[1]), "r"(a[2]), "r"(a[3]), "r"(b0), "r"(b1));
}

// Scratch: q,k,v in [B,H,S,HD] (tf32-valued fp32 bits; q pre-scaled);
// att in [B,S,E] (tf32-valued); wt = tf32-rounded proj weight.
__device__ float g_q[BB*HH*SS*HD];
__device__ float g_k[BB*HH*SS*HD];
__device__ float g_v[BB*HH*SS*HD];
__device__ float g_att[BB*SS*EE];
__device__ float g_wt[EE*EE];

// ---------------------------------------------------------------------------
// Kernel 0: round proj weight to tf32 (RNA) into scratch.
// ---------------------------------------------------------------------------
__global__ void __launch_bounds__(256) wconv_kernel(const float* __restrict__ W)
{
    const int i4 = (blockIdx.x * 256 + threadIdx.x) * 4;
    float4 v = *(const float4*)(W + i4);
    uint u0, u1, u2, u3;
    CVT_TF32(u0, v.x); CVT_TF32(u1, v.y);
    CVT_TF32(u2, v.z); CVT_TF32(u3, v.w);
    *(uint4*)((uint*)g_wt + i4) = make_uint4(u0, u1, u2, u3);
}

// ---------------------------------------------------------------------------
// Kernel 1: fused QKV projection via tf32 mma, one head per block (unchanged).
// ---------------------------------------------------------------------------
#define XP 76
__global__ void __launch_bounds__(256) qkv_kernel(
    const float* __restrict__ x,
    const float* __restrict__ Wq, const float* __restrict__ bq,
    const float* __restrict__ Wk, const float* __restrict__ bk,
    const float* __restrict__ Wv, const float* __restrict__ bv)
{
    extern __shared__ float sm[];
    uint* sX = (uint*)sm;                        // [128 tok][64] pitch 76
    uint* sW = sX + 128 * XP;                    // 3 x [64 out][64 in] pitch 76
    float* sBias = (float*)(sW + 3 * 64 * XP);   // 3 x 64

    const int tid  = threadIdx.x;
    const int warp = tid >> 5;
    const int lane = tid & 31;
    const int g  = lane >> 2;
    const int qd = lane & 3;
    const int tt = blockIdx.x;
    const int h  = blockIdx.y;

    for (int i = tid; i < 128 * 16; i += 256) {
        const int r = i >> 4, c4 = (i & 15) * 4;
        float4 v = *(const float4*)(x + (long)(tt * 128 + r) * EE + h * 64 + c4);
        uint u0, u1, u2, u3;
        CVT_TF32(u0, v.x); CVT_TF32(u1, v.y);
        CVT_TF32(u2, v.z); CVT_TF32(u3, v.w);
        *(uint4*)(sX + r * XP + c4) = make_uint4(u0, u1, u2, u3);
    }
    {
        const float* Ws[3] = {Wq, Wk, Wv};
        #pragma unroll
        for (int m = 0; m < 3; ++m) {
            for (int i = tid; i < 64 * 16; i += 256) {
                const int r = i >> 4, c4 = (i & 15) * 4;
                float4 v = *(const float4*)(Ws[m] + r * 64 + c4);
                uint u0, u1, u2, u3;
                CVT_TF32(u0, v.x); CVT_TF32(u1, v.y);
                CVT_TF32(u2, v.z); CVT_TF32(u3, v.w);
                *(uint4*)(sW + (m * 64 + r) * XP + c4) = make_uint4(u0, u1, u2, u3);
            }
        }
    }
    if (tid < 64) {
        sBias[tid]       = bq[tid];
        sBias[64 + tid]  = bk[tid];
        sBias[128 + tid] = bv[tid];
    }
    __syncthreads();

    float acc[3][8][4];
    #pragma unroll
    for (int m = 0; m < 3; ++m)
        #pragma unroll
        for (int j = 0; j < 8; ++j)
            #pragma unroll
            for (int r = 0; r < 4; ++r) acc[m][j][r] = 0.f;

    const int r0w = warp * 16;

    #pragma unroll
    for (int t = 0; t < 8; ++t) {
        uint af[4];
        af[0] = sX[(r0w + g)     * XP + 8 * t + qd];
        af[1] = sX[(r0w + g + 8) * XP + 8 * t + qd];
        af[2] = sX[(r0w + g)     * XP + 8 * t + qd + 4];
        af[3] = sX[(r0w + g + 8) * XP + 8 * t + qd + 4];
        #pragma unroll
        for (int m = 0; m < 3; ++m) {
            const uint* sWm = sW + m * 64 * XP;
            #pragma unroll
            for (int j = 0; j < 8; ++j) {
                const uint b0 = sWm[(8 * j + g) * XP + 8 * t + qd];
                const uint b1 = sWm[(8 * j + g) * XP + 8 * t + qd + 4];
                mma_tf32(acc[m][j], af, b0, b1);
            }
        }
    }

    const int tok = tt * 128 + r0w + g;
    const int b = tok >> 11, s = tok & 2047;
    const long base0 = ((long)(b * HH + h) * SS + s) * HD;
    const long base1 = base0 + 8 * HD;
    uint* outs[3] = {(uint*)g_q, (uint*)g_k, (uint*)g_v};
    #pragma unroll
    for (int m = 0; m < 3; ++m) {
        const float scl = (m == 0) ? SCALE : 1.0f;
        #pragma unroll
        for (int j = 0; j < 8; ++j) {
            const int col = 8 * j + 2 * qd;
            const float b0f = sBias[m * 64 + col];
            const float b1f = sBias[m * 64 + col + 1];
            uint u0, u1;
            CVT_TF32(u0, (acc[m][j][0] + b0f) * scl);
            CVT_TF32(u1, (acc[m][j][1] + b1f) * scl);
            *(uint2*)(outs[m] + base0 + col) = make_uint2(u0, u1);
            CVT_TF32(u0, (acc[m][j][2] + b0f) * scl);
            CVT_TF32(u1, (acc[m][j][3] + b1f) * scl);
            *(uint2*)(outs[m] + base1 + col) = make_uint2(u0, u1);
        }
    }
}

// ---------------------------------------------------------------------------
// Kernel 2: causal flash attention via mma.sync tf32 (m16n8k8).
// BR=128 (8 warps x 16 rows), BC=64. Q in registers, K/V double-buffered in
// SMEM via cp.async (one __syncthreads per iteration). Pitch 72.
// Writes g_att as tf32 bit patterns for the cp.async proj.
// ---------------------------------------------------------------------------
#define PT 72
#define KVSTG (2 * 64 * PT)     // floats per K+V stage
__global__ void __launch_bounds__(256) attn_kernel()
{
    extern __shared__ float sm[];
    // [stage0: K|V][stage1: K|V][PQ]
    float* sPQ = sm + 2 * KVSTG;      // [128 rows][64] pitch 72
    uint* sPQu = (uint*)sPQ;

    const int tid  = threadIdx.x;
    const int warp = tid >> 5;
    const int lane = tid & 31;
    const int g = lane >> 2;
    const int qd = lane & 3;

    const int qb = (int)(gridDim.x - 1 - blockIdx.x);   // big blocks first
    const int h  = blockIdx.y;
    const int b  = blockIdx.z;

    const long head_off = (long)(b * HH + h) * SS * HD;
    const float* Qg = g_q + head_off;
    const float* Kg = g_k + head_off;
    const float* Vg = g_v + head_off;

    const int q0  = qb * 128;
    const int r0w = warp * 16;

    // Issue tile 0 (K,V) + Q staging via cp.async, one group
    {
        float* sK0 = sm;
        float* sV0 = sm + 64 * PT;
        #pragma unroll
        for (int u = 0; u < 4; ++u) {
            const int i  = tid + u * 256;
            const int r  = i >> 4;
            const int c4 = (i & 15) * 4;
            CPA16(sm_u32(sK0 + r * PT + c4), Kg + (long)r * HD + c4);
            CPA16(sm_u32(sV0 + r * PT + c4), Vg + (long)r * HD + c4);
        }
        #pragma unroll
        for (int u = 0; u < 8; ++u) {
            const int i  = tid + u * 256;
            const int r  = i >> 4;
            const int c4 = (i & 15) * 4;
            CPA16(sm_u32(sPQ + r * PT + c4), Qg + (long)(q0 + r) * HD + c4);
        }
        CPA_COMMIT();
    }
    CPA_WAIT0();
    __syncthreads();

    uint qf[8][4];
    #pragma unroll
    for (int t = 0; t < 8; ++t) {
        qf[t][0] = sPQu[(r0w + g)     * PT + 8 * t + qd];
        qf[t][1] = sPQu[(r0w + g + 8) * PT + 8 * t + qd];
        qf[t][2] = sPQu[(r0w + g)     * PT + 8 * t + qd + 4];
        qf[t][3] = sPQu[(r0w + g + 8) * PT + 8 * t + qd + 4];
    }
    __syncthreads();   // everyone done reading Q from sPQ before it becomes P

    float o[8][4];
    #pragma unroll
    for (int j = 0; j < 8; ++j)
        #pragma unroll
        for (int r = 0; r < 4; ++r) o[j][r] = 0.f;
    float m0 = -INFINITY, m1 = -INFINITY, l0 = 0.f, l1 = 0.f;

    const int kbmax = 2 * qb + 1;
    for (int kb = 0; kb <= kbmax; ++kb) {
        float* sK = sm + (kb & 1) * KVSTG;
        float* sV = sK + 64 * PT;
        uint* sKu = (uint*)sK;
        uint* sVu = (uint*)sV;

        // Issue next tile into the other stage buffer
        if (kb < kbmax) {
            float* dK = sm + ((kb + 1) & 1) * KVSTG;
            float* dV = dK + 64 * PT;
            const long kn = (long)(kb + 1) * 64;
            #pragma unroll
            for (int u = 0; u < 4; ++u) {
                const int i  = tid + u * 256;
                const int r  = i >> 4;
                const int c4 = (i & 15) * 4;
                CPA16(sm_u32(dK + r * PT + c4), Kg + (kn + r) * HD + c4);
                CPA16(sm_u32(dV + r * PT + c4), Vg + (kn + r) * HD + c4);
            }
            CPA_COMMIT();
        }

        const int k0 = kb * 64;

        // --- S = Q @ K^T ---
        float sc[8][4];
        #pragma unroll
        for (int j = 0; j < 8; ++j)
            #pragma unroll
            for (int r = 0; r < 4; ++r) sc[j][r] = 0.f;

        #pragma unroll
        for (int t = 0; t < 8; ++t) {
            #pragma unroll
            for (int j = 0; j < 8; ++j) {
                const uint b0 = sKu[(8 * j + g) * PT + 8 * t + qd];
                const uint b1 = sKu[(8 * j + g) * PT + 8 * t + qd + 4];
                mma_tf32(sc[j], qf[t], b0, b1);
            }
        }

        // Causal mask
        if (kb >= 2 * qb) {
            const int row0 = q0 + r0w + g;
            const int row1 = row0 + 8;
            #pragma unroll
            for (int j = 0; j < 8; ++j) {
                const int c0 = k0 + 8 * j + 2 * qd;
                if (c0     > row0) sc[j][0] = -1e20f;
                if (c0 + 1 > row0) sc[j][1] = -1e20f;
                if (c0     > row1) sc[j][2] = -1e20f;
                if (c0 + 1 > row1) sc[j][3] = -1e20f;
            }
        }

        // --- Online softmax ---
        float mx0 = -INFINITY, mx1 = -INFINITY;
        #pragma unroll
        for (int j = 0; j < 8; ++j) {
            mx0 = fmaxf(mx0, fmaxf(sc[j][0], sc[j][1]));
            mx1 = fmaxf(mx1, fmaxf(sc[j][2], sc[j][3]));
        }
        mx0 = fmaxf(mx0, __shfl_xor_sync(0xffffffffu, mx0, 1));
        mx0 = fmaxf(mx0, __shfl_xor_sync(0xffffffffu, mx0, 2));
        mx1 = fmaxf(mx1, __shfl_xor_sync(0xffffffffu, mx1, 1));
        mx1 = fmaxf(mx1, __shfl_xor_sync(0xffffffffu, mx1, 2));

        const float mn0 = fmaxf(m0, mx0);
        const float mn1 = fmaxf(m1, mx1);
        const float a0 = __expf(m0 - mn0);
        const float a1 = __expf(m1 - mn1);
        float rs0 = 0.f, rs1 = 0.f;
        #pragma unroll
        for (int j = 0; j < 8; ++j) {
            sc[j][0] = __expf(sc[j][0] - mn0);
            sc[j][1] = __expf(sc[j][1] - mn0);
            sc[j][2] = __expf(sc[j][2] - mn1);
            sc[j][3] = __expf(sc[j][3] - mn1);
            rs0 += sc[j][0] + sc[j][1];
            rs1 += sc[j][2] + sc[j][3];
        }
        rs0 += __shfl_xor_sync(0xffffffffu, rs0, 1);
        rs0 += __shfl_xor_sync(0xffffffffu, rs0, 2);
        rs1 += __shfl_xor_sync(0xffffffffu, rs1, 1);
        rs1 += __shfl_xor_sync(0xffffffffu, rs1, 2);
        l0 = l0 * a0 + rs0;  m0 = mn0;
        l1 = l1 * a1 + rs1;  m1 = mn1;

        // P -> warp-private SMEM rows (tf32); rescale O
        #pragma unroll
        for (int j = 0; j < 8; ++j) {
            uint p0, p1, p2, p3;
            CVT_TF32(p0, sc[j][0]); CVT_TF32(p1, sc[j][1]);
            CVT_TF32(p2, sc[j][2]); CVT_TF32(p3, sc[j][3]);
            *(uint2*)(sPQu + (r0w + g)     * PT + 8 * j + 2 * qd) = make_uint2(p0, p1);
            *(uint2*)(sPQu + (r0w + g + 8) * PT + 8 * j + 2 * qd) = make_uint2(p2, p3);
            o[j][0] *= a0; o[j][1] *= a0;
            o[j][2] *= a1; o[j][3] *= a1;
        }
        __syncwarp();

        // --- O += P @ V ---
        #pragma unroll
        for (int t = 0; t < 8; ++t) {
            uint af[4];
            af[0] = sPQu[(r0w + g)     * PT + 8 * t + qd];
            af[1] = sPQu[(r0w + g + 8) * PT + 8 * t + qd];
            af[2] = sPQu[(r0w + g)     * PT + 8 * t + qd + 4];
            af[3] = sPQu[(r0w + g + 8) * PT + 8 * t + qd + 4];
            #pragma unroll
            for (int j = 0; j < 8; ++j) {
                const uint b0 = sVu[(8 * t + qd)     * PT + 8 * j + g];
                const uint b1 = sVu[(8 * t + qd + 4) * PT + 8 * j + g];
                mma_tf32(o[j], af, b0, b1);
            }
        }

        if (kb < kbmax) CPA_WAIT0();
        __syncthreads();   // next tile visible to all; protects stage reuse
    }

    // Finalize: O /= l, convert to tf32 bits, write to [B, S, H*HD]
    const float inv0 = 1.0f / l0;
    const float inv1 = 1.0f / l1;
    uint* attu = (uint*)g_att;
    const long row0 = (long)(b * SS + q0 + r0w + g) * EE + h * 64;
    const long row1 = row0 + 8 * EE;
    #pragma unroll
    for (int j = 0; j < 8; ++j) {
        const int c = 8 * j + 2 * qd;
        uint u0, u1;
        CVT_TF32(u0, o[j][0] * inv0); CVT_TF32(u1, o[j][1] * inv0);
        *(uint2*)(attu + row0 + c) = make_uint2(u0, u1);
        CVT_TF32(u0, o[j][2] * inv1); CVT_TF32(u1, o[j][3] * inv1);
        *(uint2*)(attu + row1 + c) = make_uint2(u0, u1);
    }
}

// ---------------------------------------------------------------------------
// Kernel 3: output projection via tf32 mma, cp.async double-buffered.
// Operands (g_att, g_wt) are pre-rounded tf32 bits in GMEM.
// ---------------------------------------------------------------------------
#define PP 36
#define PSTG (128 * PP)
__global__ void __launch_bounds__(256) proj_kernel(
    const float* __restrict__ bias, float* __restrict__ out)
{
    extern __shared__ float smp[];
    uint* sbuf = (uint*)smp;   // [stage][A|W], each PSTG

    const int tid  = threadIdx.x;
    const int warp = tid >> 5;
    const int lane = tid & 31;
    const int g  = lane >> 2;
    const int qd = lane & 3;

    const int jb = blockIdx.x;
    const int ib = blockIdx.y;
    const int wm = (warp >> 1) * 32;
    const int wn = (warp & 1) * 64;

    float acc[2][8][4];
    #pragma unroll
    for (int mt = 0; mt < 2; ++mt)
        #pragma unroll
        for (int j = 0; j < 8; ++j)
            #pragma unroll
            for (int r = 0; r < 4; ++r) acc[mt][j][r] = 0.f;

    // Issue stage 0
    {
        uint* dA = sbuf;
        uint* dW = sbuf + PSTG;
        #pragma unroll
        for (int u = 0; u < 4; ++u) {
            const int i = tid + u * 256;
            const int r = i >> 3, c4 = (i & 7) * 4;
            CPA16(sm_u32(dA + r * PP + c4), g_att + (long)(ib * 128 + r) * 1024 + c4);
            CPA16(sm_u32(dW + r * PP + c4), g_wt  + (long)(jb * 128 + r) * 1024 + c4);
        }
        CPA_COMMIT();
    }
    CPA_WAIT0();
    __syncthreads();

    const int NSTG = 1024 / 32;
    for (int s = 0; s < NSTG; ++s) {
        uint* sA = sbuf + (s & 1) * 2 * PSTG;
        uint* sW = sA + PSTG;

        // Issue next stage
        if (s + 1 < NSTG) {
            uint* dA = sbuf + ((s + 1) & 1) * 2 * PSTG;
            uint* dW = dA + PSTG;
            const int k0 = (s + 1) * 32;
            #pragma unroll
            for (int u = 0; u < 4; ++u) {
                const int i = tid + u * 256;
                const int r = i >> 3, c4 = (i & 7) * 4;
                CPA16(sm_u32(dA + r * PP + c4), g_att + (long)(ib * 128 + r) * 1024 + k0 + c4);
                CPA16(sm_u32(dW + r * PP + c4), g_wt  + (long)(jb * 128 + r) * 1024 + k0 + c4);
            }
            CPA_COMMIT();
        }

        #pragma unroll
        for (int t = 0; t < 4; ++t) {
            const int kk = t * 8;
            uint af0[4], af1[4];
            af0[0] = sA[(wm + g)      * PP + kk + qd];
            af0[1] = sA[(wm + g + 8)  * PP + kk + qd];
            af0[2] = sA[(wm + g)      * PP + kk + qd + 4];
            af0[3] = sA[(wm + g + 8)  * PP + kk + qd + 4];
            af1[0] = sA[(wm + g + 16) * PP + kk + qd];
            af1[1] = sA[(wm + g + 24) * PP + kk + qd];
            af1[2] = sA[(wm + g + 16) * PP + kk + qd + 4];
            af1[3] = sA[(wm + g + 24) * PP + kk + qd + 4];
            #pragma unroll
            for (int j = 0; j < 8; ++j) {
                const uint b0 = sW[(wn + 8 * j + g) * PP + kk + qd];
                const uint b1 = sW[(wn + 8 * j + g) * PP + kk + qd + 4];
                mma_tf32(acc[0][j], af0, b0, b1);
                mma_tf32(acc[1][j], af1, b0, b1);
            }
        }

        if (s + 1 < NSTG) CPA_WAIT0();
        __syncthreads();
    }

    #pragma unroll
    for (int mt = 0; mt < 2; ++mt) {
        const int rbase = ib * 128 + wm + mt * 16;
        #pragma unroll
        for (int j = 0; j < 8; ++j) {
            const int col = jb * 128 + wn + 8 * j + 2 * qd;
            const float b0 = bias[col], b1 = bias[col + 1];
            float* p0 = out + (long)(rbase + g) * 1024 + col;
            float* p1 = out + (long)(rbase + g + 8) * 1024 + col;
            *(float2*)p0 = make_float2(acc[mt][j][0] + b0, acc[mt][j][1] + b1);
            *(float2*)p1 = make_float2(acc[mt][j][2] + b0, acc[mt][j][3] + b1);
        }
    }
}

// ---------------------------------------------------------------------------
extern "C" void kernel_launch(void* const* d_in, const int* in_sizes, int n_in,
                              void* d_out, int out_size)
{
    const float* x   = (const float*)d_in[0];
    const float* Wq  = (const float*)d_in[1];
    const float* bq  = (const float*)d_in[2];
    const float* Wk  = (const float*)d_in[3];
    const float* bk  = (const float*)d_in[4];
    const float* Wv  = (const float*)d_in[5];
    const float* bv  = (const float*)d_in[6];
    const float* pw  = (const float*)d_in[7];
    const float* pb  = (const float*)d_in[8];
    float* out = (float*)d_out;

    const int qkv_smem  = (128 * XP + 3 * 64 * XP) * (int)sizeof(float) + 3 * 64 * (int)sizeof(float);
    const int attn_smem = (2 * KVSTG + 128 * PT) * (int)sizeof(float);   // 110.6 KB
    const int proj_smem = 4 * PSTG * (int)sizeof(float);                 // 73.7 KB
    cudaFuncSetAttribute(qkv_kernel,  cudaFuncAttributeMaxDynamicSharedMemorySize, qkv_smem);
    cudaFuncSetAttribute(attn_kernel, cudaFuncAttributeMaxDynamicSharedMemorySize, attn_smem);
    cudaFuncSetAttribute(proj_kernel, cudaFuncAttributeMaxDynamicSharedMemorySize, proj_smem);

    wconv_kernel<<<EE * EE / (256 * 4), 256>>>(pw);
    qkv_kernel<<<dim3((BB * SS) / 128, HH), 256, qkv_smem>>>(x, Wq, bq, Wk, bk, Wv, bv);
    attn_kernel<<<dim3(SS / 128, HH, BB), 256, attn_smem>>>();
    proj_kernel<<<dim3(EE / 128, (BB * SS) / 128), 256, proj_smem>>>(pb, out);
}